// round 5
// baseline (speedup 1.0000x reference)
#include <cuda_runtime.h>
#include <cuda_bf16.h>
#include <cstdint>
#include <math.h>

#define Bv 8
#define Fv 4
#define Tv 1024
#define Sv 1024
#define Cv 32
#define C2v 64
#define NHv 2
#define HDv 16

// Scratch (device globals: no allocation allowed)
__device__ float g_q[Bv*Fv*Tv*Cv];   // 4 MB
__device__ float g_k[Bv*Sv*Cv];      // 1 MB
__device__ float g_v[Bv*Sv*Cv];      // 1 MB
__device__ float g_y[Bv*Fv*Tv*Cv];   // 4 MB

__device__ __forceinline__ float gelu_f(float x) {
    return 0.5f * x * (1.0f + erff(x * 0.7071067811865476f));
}

__device__ __forceinline__ uint32_t f2tf32(float f) {
    uint32_t u;
    asm("cvt.rna.tf32.f32 %0, %1;" : "=r"(u) : "f"(f));
    return u;
}

__device__ __forceinline__ uint32_t pack_bf16x2(float lo, float hi) {
    __nv_bfloat162 p = __floats2bfloat162_rn(lo, hi);   // x=lo, y=hi
    return *reinterpret_cast<uint32_t*>(&p);
}

__device__ __forceinline__ void mma_tf32(float c[4], const uint32_t a[4], const uint32_t b[2]) {
    asm volatile(
        "mma.sync.aligned.m16n8k8.row.col.f32.tf32.tf32.f32 "
        "{%0,%1,%2,%3},{%4,%5,%6,%7},{%8,%9},{%0,%1,%2,%3};"
        : "+f"(c[0]), "+f"(c[1]), "+f"(c[2]), "+f"(c[3])
        : "r"(a[0]), "r"(a[1]), "r"(a[2]), "r"(a[3]), "r"(b[0]), "r"(b[1]));
}

__device__ __forceinline__ void mma_bf16(float c[4], const uint32_t a[4], const uint32_t b[2]) {
    asm volatile(
        "mma.sync.aligned.m16n8k16.row.col.f32.bf16.bf16.f32 "
        "{%0,%1,%2,%3},{%4,%5,%6,%7},{%8,%9},{%0,%1,%2,%3};"
        : "+f"(c[0]), "+f"(c[1]), "+f"(c[2]), "+f"(c[3])
        : "r"(a[0]), "r"(a[1]), "r"(a[2]), "r"(a[3]), "r"(b[0]), "r"(b[1]));
}

// ---------------------------------------------------------------------------
// Fused TCL: one launch covers q (256 tiles), k (64), v (64) = 384 blocks.
// Block id selects role, sequence, tile and weight set. Body = round-1 TCL.
// ---------------------------------------------------------------------------
__global__ __launch_bounds__(128) void tcl_fused_kernel(
    const float* __restrict__ causal, const float* __restrict__ pastkv,
    float* __restrict__ qo, float* __restrict__ ko, float* __restrict__ vo,
    const float* __restrict__ wqc, const float* __restrict__ bqc,
    const float* __restrict__ wqp, const float* __restrict__ bqp,
    const float* __restrict__ wkc, const float* __restrict__ bkc,
    const float* __restrict__ wkp, const float* __restrict__ bkp,
    const float* __restrict__ wvc, const float* __restrict__ bvc,
    const float* __restrict__ wvp, const float* __restrict__ bvp)
{
    __shared__ __align__(16) float ws[C2v*3*Cv];   // [o][k][c]
    __shared__ __align__(16) float wps[C2v*Cv];    // [o][c]
    __shared__ float bcs[C2v];
    __shared__ __align__(16) float bps[Cv];

    const int bid = blockIdx.x;
    const float *x, *wconv, *bconv, *wproj, *bproj;
    float* out;
    int n, tile;
    if (bid < 256) {
        x = causal; out = qo;
        wconv = wqc; bconv = bqc; wproj = wqp; bproj = bqp;
        n = bid >> 3; tile = bid & 7;
    } else if (bid < 320) {
        x = pastkv; out = ko;
        wconv = wkc; bconv = bkc; wproj = wkp; bproj = bkp;
        int idx = bid - 256; n = idx >> 3; tile = idx & 7;
    } else {
        x = pastkv; out = vo;
        wconv = wvc; bconv = bvc; wproj = wvp; bproj = bvp;
        int idx = bid - 320; n = idx >> 3; tile = idx & 7;
    }

    int tid = threadIdx.x;
    for (int i = tid; i < C2v*3*Cv; i += 128) {
        int o = i / (3*Cv); int rem = i % (3*Cv); int kk = rem / Cv; int c = rem % Cv;
        ws[i] = wconv[(o*Cv + c)*3 + kk];
    }
    for (int i = tid; i < C2v*Cv; i += 128) {
        int o = i / Cv; int c = i % Cv;
        wps[i] = wproj[c*C2v + o];
    }
    if (tid < C2v) bcs[tid] = bconv[tid];
    if (tid < Cv)  bps[tid] = bproj[tid];
    __syncthreads();

    int t = tile * 128 + tid;

    float4 xr[3][8];
    #pragma unroll
    for (int kk = 0; kk < 3; kk++) {
        int tt = t - 2 + kk;
        if (tt >= 0) {
            const float4* p = (const float4*)(x + ((long)n*1024 + tt)*Cv);
            #pragma unroll
            for (int cc = 0; cc < 8; cc++) xr[kk][cc] = p[cc];
        } else {
            #pragma unroll
            for (int cc = 0; cc < 8; cc++) xr[kk][cc] = make_float4(0.f,0.f,0.f,0.f);
        }
    }

    float4 acc[8];
    #pragma unroll
    for (int cc = 0; cc < 8; cc++)
        acc[cc] = make_float4(bps[cc*4+0], bps[cc*4+1], bps[cc*4+2], bps[cc*4+3]);

    #pragma unroll 2
    for (int o = 0; o < C2v; o++) {
        float s = bcs[o];
        #pragma unroll
        for (int kk = 0; kk < 3; kk++) {
            const float4* w4 = (const float4*)(ws + (o*3 + kk)*Cv);
            #pragma unroll
            for (int cc = 0; cc < 8; cc++) {
                float4 w = w4[cc];
                float4 xv = xr[kk][cc];
                s += w.x*xv.x + w.y*xv.y + w.z*xv.z + w.w*xv.w;
            }
        }
        s = gelu_f(s);
        const float4* wp4 = (const float4*)(wps + o*Cv);
        #pragma unroll
        for (int cc = 0; cc < 8; cc++) {
            float4 w = wp4[cc];
            acc[cc].x += s*w.x; acc[cc].y += s*w.y; acc[cc].z += s*w.z; acc[cc].w += s*w.w;
        }
    }

    float4* orow = (float4*)(out + ((long)n*1024 + t)*Cv);
    #pragma unroll
    for (int cc = 0; cc < 8; cc++) orow[cc] = acc[cc];
}

// ---------------------------------------------------------------------------
// Attention v3: tf32 QK^T + bf16 P*V (FA2 register-layout trick, no shuffles).
// Warp = 16 q rows; block = 8 warps = 128 rows; grid (32, 2, 8) = 512 blocks.
// S chunked by 64; no-max softmax (exact; clamped at 80).
// ---------------------------------------------------------------------------
#define CH 64          // s-chunk length
#define KSTR 20        // Ks row stride (floats): conflict-free B-frag gathers
#define VSTR 24        // Vp pair-row stride (u32): conflict-free bf16 B-frag gathers

__global__ __launch_bounds__(256) void attn_mma_kernel(
    const float* __restrict__ q, const float* __restrict__ k,
    const float* __restrict__ v, float* __restrict__ y)
{
    __shared__ float    Ks[CH*KSTR];          // tf32 K tile [s][d]
    __shared__ uint32_t Vp[(CH/2)*VSTR];      // bf16x2 V pairs [s/2][d] (lo=s even, hi=s odd)

    const int tid = threadIdx.x;
    const int w   = tid >> 5;
    const int l   = tid & 31;
    const int lq  = l >> 2;
    const int lr  = l & 3;
    const int b   = blockIdx.z, h = blockIdx.y;

    const int rowbase = blockIdx.x * 128 + w * 16;
    const int f  = rowbase >> 10;
    const int t0 = rowbase & 1023;
    const float* qbase = q + (((long)(b*Fv + f))*Tv + t0)*Cv + h*HDv;

    // Q fragments (prescaled by 0.25 = 1/sqrt(hd)), tf32: [kstep][4]
    uint32_t qa[2][4];
    #pragma unroll
    for (int ks = 0; ks < 2; ks++) {
        int c0 = ks*8 + lr;
        qa[ks][0] = f2tf32(qbase[(long)lq*Cv + c0]         * 0.25f);
        qa[ks][1] = f2tf32(qbase[(long)(lq+8)*Cv + c0]     * 0.25f);
        qa[ks][2] = f2tf32(qbase[(long)lq*Cv + c0+4]       * 0.25f);
        qa[ks][3] = f2tf32(qbase[(long)(lq+8)*Cv + c0+4]   * 0.25f);
    }

    float O[2][4];            // [dn (d0=0/8)][4]
    #pragma unroll
    for (int i = 0; i < 2; i++)
        #pragma unroll
        for (int e = 0; e < 4; e++) O[i][e] = 0.f;
    float ls[2] = {0.f, 0.f}; // row-sum partials (row lq, row lq+8)

    const float* kb = k + ((long)b*Sv)*Cv + h*HDv;
    const float* vb = v + ((long)b*Sv)*Cv + h*HDv;

    for (int chunk = 0; chunk < Sv/CH; chunk++) {
        int s0 = chunk * CH;
        __syncthreads();
        // Stage K (tf32) and V (bf16x2 pairs along s)
        for (int i = tid; i < CH*16; i += 256) {
            int s = i >> 4, d = i & 15;
            Ks[s*KSTR + d] = __uint_as_float(f2tf32(kb[(long)(s0+s)*Cv + d]));
        }
        for (int i = tid; i < (CH/2)*16; i += 256) {
            int s2 = i >> 4, d = i & 15;
            Vp[s2*VSTR + d] = pack_bf16x2(vb[(long)(s0+2*s2)*Cv + d],
                                          vb[(long)(s0+2*s2+1)*Cv + d]);
        }
        __syncthreads();

        #pragma unroll
        for (int ntp = 0; ntp < CH/16; ntp++) {    // 16-s slices
            uint32_t pa[4];
            #pragma unroll
            for (int half = 0; half < 2; half++) { // two 8-s QK n-tiles
                int snt = ntp*16 + half*8;
                uint32_t kf[2][2];
                #pragma unroll
                for (int ks = 0; ks < 2; ks++) {
                    int dbase = ks*8 + lr;
                    kf[ks][0] = __float_as_uint(Ks[(snt + lq)*KSTR + dbase]);
                    kf[ks][1] = __float_as_uint(Ks[(snt + lq)*KSTR + dbase + 4]);
                }
                float c[4] = {0.f, 0.f, 0.f, 0.f};
                mma_tf32(c, qa[0], kf[0]);
                mma_tf32(c, qa[1], kf[1]);
                float e0 = __expf(fminf(c[0], 80.f));
                float e1 = __expf(fminf(c[1], 80.f));
                float e2 = __expf(fminf(c[2], 80.f));
                float e3 = __expf(fminf(c[3], 80.f));
                ls[0] += e0 + e1;
                ls[1] += e2 + e3;
                // C-frag (m=lq, n=2lr/2lr+1) == bf16 A-frag (m=lq, k=2lr/2lr+1): pack in place
                pa[half*2 + 0] = pack_bf16x2(e0, e1);   // rows lq
                pa[half*2 + 1] = pack_bf16x2(e2, e3);   // rows lq+8
            }
            // P (bf16) @ V (bf16): k=16 s, two 8-wide d tiles
            int s2base = ntp * 8;
            #pragma unroll
            for (int dn = 0; dn < 2; dn++) {
                uint32_t vf[2];
                vf[0] = Vp[(s2base + lr)*VSTR + dn*8 + lq];
                vf[1] = Vp[(s2base + lr + 4)*VSTR + dn*8 + lq];
                mma_bf16(O[dn], pa, vf);
            }
        }
    }

    // Reduce row-sums across the quad owning each row
    #pragma unroll
    for (int i = 0; i < 2; i++) {
        ls[i] += __shfl_xor_sync(0xffffffffu, ls[i], 1);
        ls[i] += __shfl_xor_sync(0xffffffffu, ls[i], 2);
        ls[i] = 1.0f / ls[i];
    }

    float* ybase = y + (((long)(b*Fv + f))*Tv + t0)*Cv + h*HDv;
    #pragma unroll
    for (int dn = 0; dn < 2; dn++) {
        int d0 = dn*8 + 2*lr;
        *(float2*)(ybase + (long)lq*Cv + d0)     = make_float2(O[dn][0]*ls[0], O[dn][1]*ls[0]);
        *(float2*)(ybase + (long)(lq+8)*Cv + d0) = make_float2(O[dn][2]*ls[1], O[dn][3]*ls[1]);
    }
}

// ---------------------------------------------------------------------------
// Epilogue (unchanged — known correct)
// ---------------------------------------------------------------------------
__global__ void epi_kernel(const float* __restrict__ causal, const float* __restrict__ y,
                           const float* __restrict__ wc, const float* __restrict__ lnw,
                           const float* __restrict__ wfc, const float* __restrict__ wmp,
                           float* __restrict__ out)
{
    __shared__ float wcs[32*32];
    __shared__ float wfcs[32*32];
    __shared__ float wmps[32*32];
    __shared__ float lns[32];
    __shared__ float stage[8][32];

    int tid = threadIdx.x;
    for (int i = tid; i < 1024; i += 256) {
        int a = i >> 5, bcol = i & 31;
        wcs[i]  = wc[bcol*32 + a];
        wfcs[i] = wfc[bcol*32 + a];
        wmps[i] = wmp[bcol*32 + a];
    }
    if (tid < 32) lns[tid] = lnw[tid];
    __syncthreads();

    int wid = tid >> 5, lane = tid & 31;
    long row = (long)blockIdx.x * 8 + wid;

    float yc = y[row*32 + lane];
    stage[wid][lane] = yc;
    __syncwarp();

    float o = causal[row*32 + lane];
    #pragma unroll
    for (int j = 0; j < 32; j++) o += stage[wid][j] * wcs[j*32 + lane];
    __syncwarp();

    float sum = o, sq = o*o;
    #pragma unroll
    for (int off = 16; off; off >>= 1) {
        sum += __shfl_xor_sync(0xffffffffu, sum, off);
        sq  += __shfl_xor_sync(0xffffffffu, sq, off);
    }
    float mu  = sum * (1.0f/32.0f);
    float var = sq  * (1.0f/32.0f) - mu*mu;
    float hn = (o - mu) * rsqrtf(var + 1e-5f) * lns[lane];

    stage[wid][lane] = hn;
    __syncwarp();
    float g = 0.f;
    #pragma unroll
    for (int j = 0; j < 32; j++) g += stage[wid][j] * wfcs[j*32 + lane];
    __syncwarp();
    g = gelu_f(g);
    stage[wid][lane] = g;
    __syncwarp();
    float mlp = 0.f;
    #pragma unroll
    for (int j = 0; j < 32; j++) mlp += stage[wid][j] * wmps[j*32 + lane];

    out[row*32 + lane] = o + mlp;
}

// ---------------------------------------------------------------------------
extern "C" void kernel_launch(void* const* d_in, const int* in_sizes, int n_in,
                              void* d_out, int out_size)
{
    const float* causal  = (const float*)d_in[0];
    const float* pastkv  = (const float*)d_in[1];
    const float* wq_conv = (const float*)d_in[2];
    const float* bq_conv = (const float*)d_in[3];
    const float* wq_proj = (const float*)d_in[4];
    const float* bq_proj = (const float*)d_in[5];
    const float* wk_conv = (const float*)d_in[6];
    const float* bk_conv = (const float*)d_in[7];
    const float* wk_proj = (const float*)d_in[8];
    const float* bk_proj = (const float*)d_in[9];
    const float* wv_conv = (const float*)d_in[10];
    const float* bv_conv = (const float*)d_in[11];
    const float* wv_proj = (const float*)d_in[12];
    const float* bv_proj = (const float*)d_in[13];
    const float* w_cproj = (const float*)d_in[14];
    const float* ln_w    = (const float*)d_in[15];
    const float* w_fc    = (const float*)d_in[16];
    const float* w_mlp   = (const float*)d_in[17];
    float* out = (float*)d_out;

    float *q, *k, *v, *y;
    cudaGetSymbolAddress((void**)&q, g_q);
    cudaGetSymbolAddress((void**)&k, g_k);
    cudaGetSymbolAddress((void**)&v, g_v);
    cudaGetSymbolAddress((void**)&y, g_y);

    // All three TCLs in one launch: 256 (q) + 64 (k) + 64 (v) = 384 blocks
    tcl_fused_kernel<<<384, 128>>>(causal, pastkv, q, k, v,
                                   wq_conv, bq_conv, wq_proj, bq_proj,
                                   wk_conv, bk_conv, wk_proj, bk_proj,
                                   wv_conv, bv_conv, wv_proj, bv_proj);

    // 128-row q tiles per block: grid (32, heads, batch) = 512 blocks
    attn_mma_kernel<<<dim3((Fv*Tv)/128, NHv, Bv), 256>>>(q, k, v, y);

    epi_kernel<<<(Bv*Fv*Tv)/8, 256>>>(causal, y, w_cproj, ln_w, w_fc, w_mlp, out);
}

// round 8
// speedup vs baseline: 1.5274x; 1.5274x over previous
#include <cuda_runtime.h>
#include <cuda_bf16.h>
#include <cstdint>
#include <math.h>

#define Bv 8
#define Fv 4
#define Tv 1024
#define Sv 1024
#define Cv 32
#define C2v 64
#define NHv 2
#define HDv 16
#define NSPLIT 2

// Scratch (device globals: no allocation allowed)
__device__ float g_q[Bv*Fv*Tv*Cv];    // 4 MB
__device__ float g_k[Bv*Sv*Cv];       // 1 MB
__device__ float g_v[Bv*Sv*Cv];       // 1 MB
__device__ float g_y0[Bv*Fv*Tv*Cv];   // 4 MB  (split 0 partial, unnormalized)
__device__ float g_y1[Bv*Fv*Tv*Cv];   // 4 MB  (split 1 partial, unnormalized)
__device__ float g_l[NSPLIT*Bv*NHv*Fv*Tv];  // 512 KB (partial row sums)

__device__ __forceinline__ float gelu_f(float x) {
    return 0.5f * x * (1.0f + erff(x * 0.7071067811865476f));
}

__device__ __forceinline__ uint32_t f2tf32(float f) {
    uint32_t u;
    asm("cvt.rna.tf32.f32 %0, %1;" : "=r"(u) : "f"(f));
    return u;
}

__device__ __forceinline__ uint32_t pack_bf16x2(float lo, float hi) {
    __nv_bfloat162 p = __floats2bfloat162_rn(lo, hi);   // x=lo, y=hi
    return *reinterpret_cast<uint32_t*>(&p);
}

__device__ __forceinline__ void mma_tf32(float c[4], const uint32_t a[4], const uint32_t b[2]) {
    asm volatile(
        "mma.sync.aligned.m16n8k8.row.col.f32.tf32.tf32.f32 "
        "{%0,%1,%2,%3},{%4,%5,%6,%7},{%8,%9},{%0,%1,%2,%3};"
        : "+f"(c[0]), "+f"(c[1]), "+f"(c[2]), "+f"(c[3])
        : "r"(a[0]), "r"(a[1]), "r"(a[2]), "r"(a[3]), "r"(b[0]), "r"(b[1]));
}

__device__ __forceinline__ void mma_bf16(float c[4], const uint32_t a[4], const uint32_t b[2]) {
    asm volatile(
        "mma.sync.aligned.m16n8k16.row.col.f32.bf16.bf16.f32 "
        "{%0,%1,%2,%3},{%4,%5,%6,%7},{%8,%9},{%0,%1,%2,%3};"
        : "+f"(c[0]), "+f"(c[1]), "+f"(c[2]), "+f"(c[3])
        : "r"(a[0]), "r"(a[1]), "r"(a[2]), "r"(a[3]), "r"(b[0]), "r"(b[1]));
}

// ---------------------------------------------------------------------------
// Fused TCL (unchanged from round 5 — works, 74.5us; next round's target)
// ---------------------------------------------------------------------------
__global__ __launch_bounds__(128) void tcl_fused_kernel(
    const float* __restrict__ causal, const float* __restrict__ pastkv,
    float* __restrict__ qo, float* __restrict__ ko, float* __restrict__ vo,
    const float* __restrict__ wqc, const float* __restrict__ bqc,
    const float* __restrict__ wqp, const float* __restrict__ bqp,
    const float* __restrict__ wkc, const float* __restrict__ bkc,
    const float* __restrict__ wkp, const float* __restrict__ bkp,
    const float* __restrict__ wvc, const float* __restrict__ bvc,
    const float* __restrict__ wvp, const float* __restrict__ bvp)
{
    __shared__ __align__(16) float ws[C2v*3*Cv];   // [o][k][c]
    __shared__ __align__(16) float wps[C2v*Cv];    // [o][c]
    __shared__ float bcs[C2v];
    __shared__ __align__(16) float bps[Cv];

    const int bid = blockIdx.x;
    const float *x, *wconv, *bconv, *wproj, *bproj;
    float* out;
    int n, tile;
    if (bid < 256) {
        x = causal; out = qo;
        wconv = wqc; bconv = bqc; wproj = wqp; bproj = bqp;
        n = bid >> 3; tile = bid & 7;
    } else if (bid < 320) {
        x = pastkv; out = ko;
        wconv = wkc; bconv = bkc; wproj = wkp; bproj = bkp;
        int idx = bid - 256; n = idx >> 3; tile = idx & 7;
    } else {
        x = pastkv; out = vo;
        wconv = wvc; bconv = bvc; wproj = wvp; bproj = bvp;
        int idx = bid - 320; n = idx >> 3; tile = idx & 7;
    }

    int tid = threadIdx.x;
    for (int i = tid; i < C2v*3*Cv; i += 128) {
        int o = i / (3*Cv); int rem = i % (3*Cv); int kk = rem / Cv; int c = rem % Cv;
        ws[i] = wconv[(o*Cv + c)*3 + kk];
    }
    for (int i = tid; i < C2v*Cv; i += 128) {
        int o = i / Cv; int c = i % Cv;
        wps[i] = wproj[c*C2v + o];
    }
    if (tid < C2v) bcs[tid] = bconv[tid];
    if (tid < Cv)  bps[tid] = bproj[tid];
    __syncthreads();

    int t = tile * 128 + tid;

    float4 xr[3][8];
    #pragma unroll
    for (int kk = 0; kk < 3; kk++) {
        int tt = t - 2 + kk;
        if (tt >= 0) {
            const float4* p = (const float4*)(x + ((long)n*1024 + tt)*Cv);
            #pragma unroll
            for (int cc = 0; cc < 8; cc++) xr[kk][cc] = p[cc];
        } else {
            #pragma unroll
            for (int cc = 0; cc < 8; cc++) xr[kk][cc] = make_float4(0.f,0.f,0.f,0.f);
        }
    }

    float4 acc[8];
    #pragma unroll
    for (int cc = 0; cc < 8; cc++)
        acc[cc] = make_float4(bps[cc*4+0], bps[cc*4+1], bps[cc*4+2], bps[cc*4+3]);

    #pragma unroll 2
    for (int o = 0; o < C2v; o++) {
        float s = bcs[o];
        #pragma unroll
        for (int kk = 0; kk < 3; kk++) {
            const float4* w4 = (const float4*)(ws + (o*3 + kk)*Cv);
            #pragma unroll
            for (int cc = 0; cc < 8; cc++) {
                float4 w = w4[cc];
                float4 xv = xr[kk][cc];
                s += w.x*xv.x + w.y*xv.y + w.z*xv.z + w.w*xv.w;
            }
        }
        s = gelu_f(s);
        const float4* wp4 = (const float4*)(wps + o*Cv);
        #pragma unroll
        for (int cc = 0; cc < 8; cc++) {
            float4 w = wp4[cc];
            acc[cc].x += s*w.x; acc[cc].y += s*w.y; acc[cc].z += s*w.z; acc[cc].w += s*w.w;
        }
    }

    float4* orow = (float4*)(out + ((long)n*1024 + t)*Cv);
    #pragma unroll
    for (int cc = 0; cc < 8; cc++) orow[cc] = acc[cc];
}

// ---------------------------------------------------------------------------
// Attention v4: round-4 tiling (32 q rows/warp, 256 rows/block) + bf16 PV
// (no shuffles) + split-S (each block does S/2; partial O,l written).
// Grid (16, NHv*NSPLIT, Bv) = 512 blocks. No-max softmax (exact; clamp 80).
// ---------------------------------------------------------------------------
#define CH 64          // s-chunk length
#define KSTR 20        // Ks row stride (floats)
#define VSTR 24        // Vp pair-row stride (u32)

__global__ __launch_bounds__(256) void attn_mma_kernel(
    const float* __restrict__ q, const float* __restrict__ k,
    const float* __restrict__ v,
    float* __restrict__ y0, float* __restrict__ y1, float* __restrict__ lpart)
{
    __shared__ float    Ks[CH*KSTR];
    __shared__ uint32_t Vp[(CH/2)*VSTR];

    const int tid = threadIdx.x;
    const int w   = tid >> 5;
    const int l   = tid & 31;
    const int lq  = l >> 2;
    const int lr  = l & 3;
    const int b     = blockIdx.z;
    const int h     = blockIdx.y >> 1;
    const int split = blockIdx.y & 1;

    const int rowbase = blockIdx.x * 256 + w * 32;   // f*1024 + t0, 32-aligned
    const int f  = rowbase >> 10;
    const int t0 = rowbase & 1023;
    const float* qbase = q + (((long)(b*Fv + f))*Tv + t0)*Cv + h*HDv;

    // Q fragments [mtile][kstep][4], prescaled 0.25, tf32
    uint32_t qa[2][2][4];
    #pragma unroll
    for (int mt = 0; mt < 2; mt++)
        #pragma unroll
        for (int ks = 0; ks < 2; ks++) {
            int r0 = mt*16 + lq;
            int c0 = ks*8 + lr;
            qa[mt][ks][0] = f2tf32(qbase[(long)r0*Cv + c0]       * 0.25f);
            qa[mt][ks][1] = f2tf32(qbase[(long)(r0+8)*Cv + c0]   * 0.25f);
            qa[mt][ks][2] = f2tf32(qbase[(long)r0*Cv + c0+4]     * 0.25f);
            qa[mt][ks][3] = f2tf32(qbase[(long)(r0+8)*Cv + c0+4] * 0.25f);
        }

    float O[2][2][4];   // [mtile][dn][4]
    #pragma unroll
    for (int i = 0; i < 2; i++)
        #pragma unroll
        for (int j = 0; j < 2; j++)
            #pragma unroll
            for (int e = 0; e < 4; e++) O[i][j][e] = 0.f;
    float ls[4] = {0.f, 0.f, 0.f, 0.f};

    const float* kb = k + ((long)b*Sv)*Cv + h*HDv;
    const float* vb = v + ((long)b*Sv)*Cv + h*HDv;
    const int sbase = split * (Sv/NSPLIT);

    for (int chunk = 0; chunk < (Sv/NSPLIT)/CH; chunk++) {
        int s0 = sbase + chunk * CH;
        __syncthreads();
        for (int i = tid; i < CH*16; i += 256) {
            int s = i >> 4, d = i & 15;
            Ks[s*KSTR + d] = __uint_as_float(f2tf32(kb[(long)(s0+s)*Cv + d]));
        }
        for (int i = tid; i < (CH/2)*16; i += 256) {
            int s2 = i >> 4, d = i & 15;
            Vp[s2*VSTR + d] = pack_bf16x2(vb[(long)(s0+2*s2)*Cv + d],
                                          vb[(long)(s0+2*s2+1)*Cv + d]);
        }
        __syncthreads();

        #pragma unroll
        for (int ntp = 0; ntp < CH/16; ntp++) {    // 16-s slices
            uint32_t pa[2][4];
            #pragma unroll
            for (int half = 0; half < 2; half++) {
                int snt = ntp*16 + half*8;
                uint32_t kf[2][2];
                #pragma unroll
                for (int ks = 0; ks < 2; ks++) {
                    int dbase = ks*8 + lr;
                    kf[ks][0] = __float_as_uint(Ks[(snt + lq)*KSTR + dbase]);
                    kf[ks][1] = __float_as_uint(Ks[(snt + lq)*KSTR + dbase + 4]);
                }
                #pragma unroll
                for (int mt = 0; mt < 2; mt++) {
                    float c[4] = {0.f, 0.f, 0.f, 0.f};
                    mma_tf32(c, qa[mt][0], kf[0]);
                    mma_tf32(c, qa[mt][1], kf[1]);
                    float e0 = __expf(fminf(c[0], 80.f));
                    float e1 = __expf(fminf(c[1], 80.f));
                    float e2 = __expf(fminf(c[2], 80.f));
                    float e3 = __expf(fminf(c[3], 80.f));
                    ls[mt*2]   += e0 + e1;
                    ls[mt*2+1] += e2 + e3;
                    pa[mt][half*2 + 0] = pack_bf16x2(e0, e1);   // rows lq
                    pa[mt][half*2 + 1] = pack_bf16x2(e2, e3);   // rows lq+8
                }
            }
            int s2base = ntp * 8;
            #pragma unroll
            for (int dn = 0; dn < 2; dn++) {
                uint32_t vf[2];
                vf[0] = Vp[(s2base + lr)*VSTR + dn*8 + lq];
                vf[1] = Vp[(s2base + lr + 4)*VSTR + dn*8 + lq];
                mma_bf16(O[0][dn], pa[0], vf);
                mma_bf16(O[1][dn], pa[1], vf);
            }
        }
    }

    // Full row sums within quads
    #pragma unroll
    for (int i = 0; i < 4; i++) {
        ls[i] += __shfl_xor_sync(0xffffffffu, ls[i], 1);
        ls[i] += __shfl_xor_sync(0xffffffffu, ls[i], 2);
    }

    // Write unnormalized partial O
    float* yout = (split ? y1 : y0) + (((long)(b*Fv + f))*Tv + t0)*Cv + h*HDv;
    #pragma unroll
    for (int mt = 0; mt < 2; mt++)
        #pragma unroll
        for (int dn = 0; dn < 2; dn++) {
            int d0 = dn*8 + 2*lr;
            int r0 = mt*16 + lq;
            *(float2*)(yout + (long)r0*Cv + d0)     = make_float2(O[mt][dn][0], O[mt][dn][1]);
            *(float2*)(yout + (long)(r0+8)*Cv + d0) = make_float2(O[mt][dn][2], O[mt][dn][3]);
        }

    // Write partial row sums (one lane per quad)
    if (lr == 0) {
        long lb = ((long)(split*Bv + b)*NHv + h)*(Fv*Tv) + rowbase;
        #pragma unroll
        for (int mt = 0; mt < 2; mt++) {
            lpart[lb + mt*16 + lq]     = ls[mt*2];
            lpart[lb + mt*16 + lq + 8] = ls[mt*2+1];
        }
    }
}

// ---------------------------------------------------------------------------
// Epilogue: combines split partials (y=(O0+O1)/(l0+l1)) then cproj+LN+MLP.
// ---------------------------------------------------------------------------
__global__ void epi_kernel(const float* __restrict__ causal,
                           const float* __restrict__ y0, const float* __restrict__ y1,
                           const float* __restrict__ lpart,
                           const float* __restrict__ wc, const float* __restrict__ lnw,
                           const float* __restrict__ wfc, const float* __restrict__ wmp,
                           float* __restrict__ out)
{
    __shared__ float wcs[32*32];
    __shared__ float wfcs[32*32];
    __shared__ float wmps[32*32];
    __shared__ float lns[32];
    __shared__ float stage[8][32];

    int tid = threadIdx.x;
    for (int i = tid; i < 1024; i += 256) {
        int a = i >> 5, bcol = i & 31;
        wcs[i]  = wc[bcol*32 + a];
        wfcs[i] = wfc[bcol*32 + a];
        wmps[i] = wmp[bcol*32 + a];
    }
    if (tid < 32) lns[tid] = lnw[tid];
    __syncthreads();

    int wid = tid >> 5, lane = tid & 31;
    long row = (long)blockIdx.x * 8 + wid;    // (b*Fv+f)*Tv + t, < 32768
    int b  = (int)(row >> 12);
    int ft = (int)(row & 4095);
    int h  = lane >> 4;

    long lidx = ((long)b*NHv + h)*(Fv*Tv) + ft;
    float lsum = lpart[lidx] + lpart[(long)Bv*NHv*Fv*Tv + lidx];
    float yc = (y0[row*32 + lane] + y1[row*32 + lane]) / lsum;
    stage[wid][lane] = yc;
    __syncwarp();

    float o = causal[row*32 + lane];
    #pragma unroll
    for (int j = 0; j < 32; j++) o += stage[wid][j] * wcs[j*32 + lane];
    __syncwarp();

    float sum = o, sq = o*o;
    #pragma unroll
    for (int off = 16; off; off >>= 1) {
        sum += __shfl_xor_sync(0xffffffffu, sum, off);
        sq  += __shfl_xor_sync(0xffffffffu, sq, off);
    }
    float mu  = sum * (1.0f/32.0f);
    float var = sq  * (1.0f/32.0f) - mu*mu;
    float hn = (o - mu) * rsqrtf(var + 1e-5f) * lns[lane];

    stage[wid][lane] = hn;
    __syncwarp();
    float g = 0.f;
    #pragma unroll
    for (int j = 0; j < 32; j++) g += stage[wid][j] * wfcs[j*32 + lane];
    __syncwarp();
    g = gelu_f(g);
    stage[wid][lane] = g;
    __syncwarp();
    float mlp = 0.f;
    #pragma unroll
    for (int j = 0; j < 32; j++) mlp += stage[wid][j] * wmps[j*32 + lane];

    out[row*32 + lane] = o + mlp;
}

// ---------------------------------------------------------------------------
extern "C" void kernel_launch(void* const* d_in, const int* in_sizes, int n_in,
                              void* d_out, int out_size)
{
    const float* causal  = (const float*)d_in[0];
    const float* pastkv  = (const float*)d_in[1];
    const float* wq_conv = (const float*)d_in[2];
    const float* bq_conv = (const float*)d_in[3];
    const float* wq_proj = (const float*)d_in[4];
    const float* bq_proj = (const float*)d_in[5];
    const float* wk_conv = (const float*)d_in[6];
    const float* bk_conv = (const float*)d_in[7];
    const float* wk_proj = (const float*)d_in[8];
    const float* bk_proj = (const float*)d_in[9];
    const float* wv_conv = (const float*)d_in[10];
    const float* bv_conv = (const float*)d_in[11];
    const float* wv_proj = (const float*)d_in[12];
    const float* bv_proj = (const float*)d_in[13];
    const float* w_cproj = (const float*)d_in[14];
    const float* ln_w    = (const float*)d_in[15];
    const float* w_fc    = (const float*)d_in[16];
    const float* w_mlp   = (const float*)d_in[17];
    float* out = (float*)d_out;

    float *q, *k, *v, *y0, *y1, *lp;
    cudaGetSymbolAddress((void**)&q,  g_q);
    cudaGetSymbolAddress((void**)&k,  g_k);
    cudaGetSymbolAddress((void**)&v,  g_v);
    cudaGetSymbolAddress((void**)&y0, g_y0);
    cudaGetSymbolAddress((void**)&y1, g_y1);
    cudaGetSymbolAddress((void**)&lp, g_l);

    tcl_fused_kernel<<<384, 128>>>(causal, pastkv, q, k, v,
                                   wq_conv, bq_conv, wq_proj, bq_proj,
                                   wk_conv, bk_conv, wk_proj, bk_proj,
                                   wv_conv, bv_conv, wv_proj, bv_proj);

    // 256-row q tiles, S split in 2: grid (16, NHv*NSPLIT, Bv) = 512 blocks
    attn_mma_kernel<<<dim3((Fv*Tv)/256, NHv*NSPLIT, Bv), 256>>>(q, k, v, y0, y1, lp);

    epi_kernel<<<(Bv*Fv*Tv)/8, 256>>>(causal, y0, y1, lp, w_cproj, ln_w, w_fc, w_mlp, out);
}

// round 10
// speedup vs baseline: 2.0200x; 1.3225x over previous
#include <cuda_runtime.h>
#include <cuda_bf16.h>
#include <cstdint>
#include <math.h>

#define Bv 8
#define Fv 4
#define Tv 1024
#define Sv 1024
#define Cv 32
#define C2v 64
#define NHv 2
#define HDv 16
#define NSPLIT 2

// Scratch (device globals: no allocation allowed)
__device__ float g_q[Bv*Fv*Tv*Cv];    // 4 MB
__device__ float g_k[Bv*Sv*Cv];       // 1 MB
__device__ float g_v[Bv*Sv*Cv];       // 1 MB
__device__ float g_y0[Bv*Fv*Tv*Cv];   // 4 MB  (split 0 partial, unnormalized)
__device__ float g_y1[Bv*Fv*Tv*Cv];   // 4 MB  (split 1 partial, unnormalized)
__device__ float g_l[NSPLIT*Bv*NHv*Fv*Tv];  // 512 KB (partial row sums)

__device__ __forceinline__ float gelu_f(float x) {
    return 0.5f * x * (1.0f + erff(x * 0.7071067811865476f));
}

// tanh-approx gelu (HW tanh.approx): |err| <= ~3e-4 absolute; suppressed ~500x
// at the output by the exact residual path.
__device__ __forceinline__ float gelu_t(float x) {
    float u = 0.7978845608028654f * x * (1.0f + 0.044715f * x * x);
    float t;
    asm("tanh.approx.f32 %0, %1;" : "=f"(t) : "f"(u));
    return 0.5f * x * (1.0f + t);
}

__device__ __forceinline__ uint32_t f2tf32(float f) {
    uint32_t u;
    asm("cvt.rna.tf32.f32 %0, %1;" : "=r"(u) : "f"(f));
    return u;
}

__device__ __forceinline__ uint32_t pack_bf16x2(float lo, float hi) {
    __nv_bfloat162 p = __floats2bfloat162_rn(lo, hi);   // x=lo, y=hi
    return *reinterpret_cast<uint32_t*>(&p);
}

__device__ __forceinline__ void mma_tf32(float c[4], const uint32_t a[4], const uint32_t b[2]) {
    asm volatile(
        "mma.sync.aligned.m16n8k8.row.col.f32.tf32.tf32.f32 "
        "{%0,%1,%2,%3},{%4,%5,%6,%7},{%8,%9},{%0,%1,%2,%3};"
        : "+f"(c[0]), "+f"(c[1]), "+f"(c[2]), "+f"(c[3])
        : "r"(a[0]), "r"(a[1]), "r"(a[2]), "r"(a[3]), "r"(b[0]), "r"(b[1]));
}

__device__ __forceinline__ void mma_bf16(float c[4], const uint32_t a[4], const uint32_t b[2]) {
    asm volatile(
        "mma.sync.aligned.m16n8k16.row.col.f32.bf16.bf16.f32 "
        "{%0,%1,%2,%3},{%4,%5,%6,%7},{%8,%9},{%0,%1,%2,%3};"
        : "+f"(c[0]), "+f"(c[1]), "+f"(c[2]), "+f"(c[3])
        : "r"(a[0]), "r"(a[1]), "r"(a[2]), "r"(a[3]), "r"(b[0]), "r"(b[1]));
}

// ---------------------------------------------------------------------------
// TCL v2 (tensor-core): im2col X[128x96] @ Wconv^T[96x64] (bf16 mma), bias +
// gelu(tanh.approx) + in-register repack to A-frags, then @ Wproj^T[64x32].
// Block = 128 thr (4 warps x 32 positions). Grid = 48 streams x 8 tiles = 384.
// All SMEM fragment gathers conflict-free via stride 52 (bank = 20*lq+lr).
// ---------------------------------------------------------------------------
#define XSTR 52

__global__ __launch_bounds__(128) void tcl_mma_kernel(
    const float* __restrict__ causal, const float* __restrict__ pastkv,
    float* __restrict__ qo, float* __restrict__ ko, float* __restrict__ vo,
    const float* __restrict__ wqc, const float* __restrict__ bqc,
    const float* __restrict__ wqp, const float* __restrict__ bqp,
    const float* __restrict__ wkc, const float* __restrict__ bkc,
    const float* __restrict__ wkp, const float* __restrict__ bkp,
    const float* __restrict__ wvc, const float* __restrict__ bvc,
    const float* __restrict__ wvp, const float* __restrict__ bvp)
{
    __shared__ uint32_t Xp[128*XSTR];   // im2col bf16x2 pairs [row][kp], kp<48
    __shared__ uint32_t Wcp[64*XSTR];   // conv W bf16x2 pairs [n][kp], kp<48
    __shared__ uint32_t Wpp[32*XSTR];   // proj W bf16x2 pairs [n][kp], kp<32
    __shared__ float bcs[C2v];
    __shared__ float bps[Cv];

    const int bid = blockIdx.x;
    const int stream = bid >> 3, tile = bid & 7;
    const float *x, *wconv, *bconv, *wproj, *bproj;
    float* out;
    if (stream < 32) {
        x = causal + (long)stream*32768; out = qo + (long)stream*32768;
        wconv = wqc; bconv = bqc; wproj = wqp; bproj = bqp;
    } else if (stream < 40) {
        int n = stream - 32;
        x = pastkv + (long)n*32768; out = ko + (long)n*32768;
        wconv = wkc; bconv = bkc; wproj = wkp; bproj = bkp;
    } else {
        int n = stream - 40;
        x = pastkv + (long)n*32768; out = vo + (long)n*32768;
        wconv = wvc; bconv = bvc; wproj = wvp; bproj = bvp;
    }

    const int tid = threadIdx.x;
    const int t0 = tile * 128;

    // Stage conv weights: W[n][k], k = tap*32 + c  ->  pairs along k
    for (int i = tid; i < 64*48; i += 128) {
        int n = i / 48, kp = i % 48;
        int tap = kp >> 4, c = (kp & 15) * 2;
        Wcp[n*XSTR + kp] = pack_bf16x2(wconv[(n*Cv + c)*3 + tap],
                                       wconv[(n*Cv + c+1)*3 + tap]);
    }
    // Stage proj weights: W2[n=c][k=o] = wproj[c*64+o], pairs along o
    for (int i = tid; i < 32*32; i += 128) {
        int n = i >> 5, kp = i & 31;
        Wpp[n*XSTR + kp] = pack_bf16x2(wproj[n*C2v + 2*kp], wproj[n*C2v + 2*kp+1]);
    }
    if (tid < C2v) bcs[tid] = bconv[tid];
    if (tid < Cv)  bps[tid] = bproj[tid];

    // Stage im2col X pairs: row r -> position t0+r; col k = tap*32 + c
    for (int i = tid; i < 128*48; i += 128) {
        int r = i / 48, kp = i % 48;
        int tap = kp >> 4, c = (kp & 15) * 2;
        int t = t0 + r - 2 + tap;
        uint32_t val = 0u;
        if (t >= 0) {
            const float* src = x + (long)t*Cv + c;
            val = pack_bf16x2(src[0], src[1]);
        }
        Xp[r*XSTR + kp] = val;
    }
    __syncthreads();

    const int w  = tid >> 5, l = tid & 31;
    const int lq = l >> 2, lr = l & 3;
    const int r0 = w * 32;

    // ---- Conv GEMM: H[32x64] per warp, K=96 (6 bf16 k16-steps) ----
    float Cc[2][8][4];
    #pragma unroll
    for (int mt = 0; mt < 2; mt++)
        #pragma unroll
        for (int nt = 0; nt < 8; nt++)
            #pragma unroll
            for (int e = 0; e < 4; e++) Cc[mt][nt][e] = 0.f;

    #pragma unroll
    for (int ks = 0; ks < 6; ks++) {
        uint32_t a[2][4];
        #pragma unroll
        for (int mt = 0; mt < 2; mt++) {
            int rr = r0 + mt*16;
            a[mt][0] = Xp[(rr+lq)*XSTR   + ks*8 + lr];
            a[mt][1] = Xp[(rr+lq+8)*XSTR + ks*8 + lr];
            a[mt][2] = Xp[(rr+lq)*XSTR   + ks*8 + lr + 4];
            a[mt][3] = Xp[(rr+lq+8)*XSTR + ks*8 + lr + 4];
        }
        #pragma unroll
        for (int nt = 0; nt < 8; nt++) {
            uint32_t bf[2];
            bf[0] = Wcp[(nt*8+lq)*XSTR + ks*8 + lr];
            bf[1] = Wcp[(nt*8+lq)*XSTR + ks*8 + lr + 4];
            mma_bf16(Cc[0][nt], a[0], bf);
            mma_bf16(Cc[1][nt], a[1], bf);
        }
    }

    // ---- bias + gelu + in-register repack: conv C-frags -> proj A-frags ----
    uint32_t pa[2][4][4];
    #pragma unroll
    for (int ks2 = 0; ks2 < 4; ks2++) {
        float b0 = bcs[(2*ks2)*8   + 2*lr], b1 = bcs[(2*ks2)*8   + 2*lr + 1];
        float b2 = bcs[(2*ks2+1)*8 + 2*lr], b3 = bcs[(2*ks2+1)*8 + 2*lr + 1];
        #pragma unroll
        for (int mt = 0; mt < 2; mt++) {
            pa[mt][ks2][0] = pack_bf16x2(gelu_t(Cc[mt][2*ks2][0]+b0),   gelu_t(Cc[mt][2*ks2][1]+b1));
            pa[mt][ks2][1] = pack_bf16x2(gelu_t(Cc[mt][2*ks2][2]+b0),   gelu_t(Cc[mt][2*ks2][3]+b1));
            pa[mt][ks2][2] = pack_bf16x2(gelu_t(Cc[mt][2*ks2+1][0]+b2), gelu_t(Cc[mt][2*ks2+1][1]+b3));
            pa[mt][ks2][3] = pack_bf16x2(gelu_t(Cc[mt][2*ks2+1][2]+b2), gelu_t(Cc[mt][2*ks2+1][3]+b3));
        }
    }

    // ---- Proj GEMM: Y[32x32] per warp, K=64 (4 k16-steps) ----
    float Cp[2][4][4];
    #pragma unroll
    for (int mt = 0; mt < 2; mt++)
        #pragma unroll
        for (int nt = 0; nt < 4; nt++)
            #pragma unroll
            for (int e = 0; e < 4; e++) Cp[mt][nt][e] = 0.f;

    #pragma unroll
    for (int ks2 = 0; ks2 < 4; ks2++) {
        #pragma unroll
        for (int nt = 0; nt < 4; nt++) {
            uint32_t bf[2];
            bf[0] = Wpp[(nt*8+lq)*XSTR + ks2*8 + lr];
            bf[1] = Wpp[(nt*8+lq)*XSTR + ks2*8 + lr + 4];
            mma_bf16(Cp[0][nt], pa[0][ks2], bf);
            mma_bf16(Cp[1][nt], pa[1][ks2], bf);
        }
    }

    // ---- bias + store ----
    #pragma unroll
    for (int mt = 0; mt < 2; mt++) {
        #pragma unroll
        for (int nt = 0; nt < 4; nt++) {
            int col = nt*8 + 2*lr;
            float bo0 = bps[col], bo1 = bps[col+1];
            long row = t0 + r0 + mt*16 + lq;
            *(float2*)(out + row*Cv + col)     = make_float2(Cp[mt][nt][0]+bo0, Cp[mt][nt][1]+bo1);
            *(float2*)(out + (row+8)*Cv + col) = make_float2(Cp[mt][nt][2]+bo0, Cp[mt][nt][3]+bo1);
        }
    }
}

// ---------------------------------------------------------------------------
// Attention v4 (unchanged from round 8 — 32 q rows/warp, bf16 PV, split-S)
// ---------------------------------------------------------------------------
#define CH 64
#define KSTR 20
#define VSTR 24

__global__ __launch_bounds__(256) void attn_mma_kernel(
    const float* __restrict__ q, const float* __restrict__ k,
    const float* __restrict__ v,
    float* __restrict__ y0, float* __restrict__ y1, float* __restrict__ lpart)
{
    __shared__ float    Ks[CH*KSTR];
    __shared__ uint32_t Vp[(CH/2)*VSTR];

    const int tid = threadIdx.x;
    const int w   = tid >> 5;
    const int l   = tid & 31;
    const int lq  = l >> 2;
    const int lr  = l & 3;
    const int b     = blockIdx.z;
    const int h     = blockIdx.y >> 1;
    const int split = blockIdx.y & 1;

    const int rowbase = blockIdx.x * 256 + w * 32;
    const int f  = rowbase >> 10;
    const int t0 = rowbase & 1023;
    const float* qbase = q + (((long)(b*Fv + f))*Tv + t0)*Cv + h*HDv;

    uint32_t qa[2][2][4];
    #pragma unroll
    for (int mt = 0; mt < 2; mt++)
        #pragma unroll
        for (int ks = 0; ks < 2; ks++) {
            int r0 = mt*16 + lq;
            int c0 = ks*8 + lr;
            qa[mt][ks][0] = f2tf32(qbase[(long)r0*Cv + c0]       * 0.25f);
            qa[mt][ks][1] = f2tf32(qbase[(long)(r0+8)*Cv + c0]   * 0.25f);
            qa[mt][ks][2] = f2tf32(qbase[(long)r0*Cv + c0+4]     * 0.25f);
            qa[mt][ks][3] = f2tf32(qbase[(long)(r0+8)*Cv + c0+4] * 0.25f);
        }

    float O[2][2][4];
    #pragma unroll
    for (int i = 0; i < 2; i++)
        #pragma unroll
        for (int j = 0; j < 2; j++)
            #pragma unroll
            for (int e = 0; e < 4; e++) O[i][j][e] = 0.f;
    float ls[4] = {0.f, 0.f, 0.f, 0.f};

    const float* kb = k + ((long)b*Sv)*Cv + h*HDv;
    const float* vb = v + ((long)b*Sv)*Cv + h*HDv;
    const int sbase = split * (Sv/NSPLIT);

    for (int chunk = 0; chunk < (Sv/NSPLIT)/CH; chunk++) {
        int s0 = sbase + chunk * CH;
        __syncthreads();
        for (int i = tid; i < CH*16; i += 256) {
            int s = i >> 4, d = i & 15;
            Ks[s*KSTR + d] = __uint_as_float(f2tf32(kb[(long)(s0+s)*Cv + d]));
        }
        for (int i = tid; i < (CH/2)*16; i += 256) {
            int s2 = i >> 4, d = i & 15;
            Vp[s2*VSTR + d] = pack_bf16x2(vb[(long)(s0+2*s2)*Cv + d],
                                          vb[(long)(s0+2*s2+1)*Cv + d]);
        }
        __syncthreads();

        #pragma unroll
        for (int ntp = 0; ntp < CH/16; ntp++) {
            uint32_t pa[2][4];
            #pragma unroll
            for (int half = 0; half < 2; half++) {
                int snt = ntp*16 + half*8;
                uint32_t kf[2][2];
                #pragma unroll
                for (int ks = 0; ks < 2; ks++) {
                    int dbase = ks*8 + lr;
                    kf[ks][0] = __float_as_uint(Ks[(snt + lq)*KSTR + dbase]);
                    kf[ks][1] = __float_as_uint(Ks[(snt + lq)*KSTR + dbase + 4]);
                }
                #pragma unroll
                for (int mt = 0; mt < 2; mt++) {
                    float c[4] = {0.f, 0.f, 0.f, 0.f};
                    mma_tf32(c, qa[mt][0], kf[0]);
                    mma_tf32(c, qa[mt][1], kf[1]);
                    float e0 = __expf(fminf(c[0], 80.f));
                    float e1 = __expf(fminf(c[1], 80.f));
                    float e2 = __expf(fminf(c[2], 80.f));
                    float e3 = __expf(fminf(c[3], 80.f));
                    ls[mt*2]   += e0 + e1;
                    ls[mt*2+1] += e2 + e3;
                    pa[mt][half*2 + 0] = pack_bf16x2(e0, e1);
                    pa[mt][half*2 + 1] = pack_bf16x2(e2, e3);
                }
            }
            int s2base = ntp * 8;
            #pragma unroll
            for (int dn = 0; dn < 2; dn++) {
                uint32_t vf[2];
                vf[0] = Vp[(s2base + lr)*VSTR + dn*8 + lq];
                vf[1] = Vp[(s2base + lr + 4)*VSTR + dn*8 + lq];
                mma_bf16(O[0][dn], pa[0], vf);
                mma_bf16(O[1][dn], pa[1], vf);
            }
        }
    }

    #pragma unroll
    for (int i = 0; i < 4; i++) {
        ls[i] += __shfl_xor_sync(0xffffffffu, ls[i], 1);
        ls[i] += __shfl_xor_sync(0xffffffffu, ls[i], 2);
    }

    float* yout = (split ? y1 : y0) + (((long)(b*Fv + f))*Tv + t0)*Cv + h*HDv;
    #pragma unroll
    for (int mt = 0; mt < 2; mt++)
        #pragma unroll
        for (int dn = 0; dn < 2; dn++) {
            int d0 = dn*8 + 2*lr;
            int r0 = mt*16 + lq;
            *(float2*)(yout + (long)r0*Cv + d0)     = make_float2(O[mt][dn][0], O[mt][dn][1]);
            *(float2*)(yout + (long)(r0+8)*Cv + d0) = make_float2(O[mt][dn][2], O[mt][dn][3]);
        }

    if (lr == 0) {
        long lb = ((long)(split*Bv + b)*NHv + h)*(Fv*Tv) + rowbase;
        #pragma unroll
        for (int mt = 0; mt < 2; mt++) {
            lpart[lb + mt*16 + lq]     = ls[mt*2];
            lpart[lb + mt*16 + lq + 8] = ls[mt*2+1];
        }
    }
}

// ---------------------------------------------------------------------------
// Epilogue (unchanged from round 8)
// ---------------------------------------------------------------------------
__global__ void epi_kernel(const float* __restrict__ causal,
                           const float* __restrict__ y0, const float* __restrict__ y1,
                           const float* __restrict__ lpart,
                           const float* __restrict__ wc, const float* __restrict__ lnw,
                           const float* __restrict__ wfc, const float* __restrict__ wmp,
                           float* __restrict__ out)
{
    __shared__ float wcs[32*32];
    __shared__ float wfcs[32*32];
    __shared__ float wmps[32*32];
    __shared__ float lns[32];
    __shared__ float stage[8][32];

    int tid = threadIdx.x;
    for (int i = tid; i < 1024; i += 256) {
        int a = i >> 5, bcol = i & 31;
        wcs[i]  = wc[bcol*32 + a];
        wfcs[i] = wfc[bcol*32 + a];
        wmps[i] = wmp[bcol*32 + a];
    }
    if (tid < 32) lns[tid] = lnw[tid];
    __syncthreads();

    int wid = tid >> 5, lane = tid & 31;
    long row = (long)blockIdx.x * 8 + wid;
    int b  = (int)(row >> 12);
    int ft = (int)(row & 4095);
    int h  = lane >> 4;

    long lidx = ((long)b*NHv + h)*(Fv*Tv) + ft;
    float lsum = lpart[lidx] + lpart[(long)Bv*NHv*Fv*Tv + lidx];
    float yc = (y0[row*32 + lane] + y1[row*32 + lane]) / lsum;
    stage[wid][lane] = yc;
    __syncwarp();

    float o = causal[row*32 + lane];
    #pragma unroll
    for (int j = 0; j < 32; j++) o += stage[wid][j] * wcs[j*32 + lane];
    __syncwarp();

    float sum = o, sq = o*o;
    #pragma unroll
    for (int off = 16; off; off >>= 1) {
        sum += __shfl_xor_sync(0xffffffffu, sum, off);
        sq  += __shfl_xor_sync(0xffffffffu, sq, off);
    }
    float mu  = sum * (1.0f/32.0f);
    float var = sq  * (1.0f/32.0f) - mu*mu;
    float hn = (o - mu) * rsqrtf(var + 1e-5f) * lns[lane];

    stage[wid][lane] = hn;
    __syncwarp();
    float g = 0.f;
    #pragma unroll
    for (int j = 0; j < 32; j++) g += stage[wid][j] * wfcs[j*32 + lane];
    __syncwarp();
    g = gelu_f(g);
    stage[wid][lane] = g;
    __syncwarp();
    float mlp = 0.f;
    #pragma unroll
    for (int j = 0; j < 32; j++) mlp += stage[wid][j] * wmps[j*32 + lane];

    out[row*32 + lane] = o + mlp;
}

// ---------------------------------------------------------------------------
extern "C" void kernel_launch(void* const* d_in, const int* in_sizes, int n_in,
                              void* d_out, int out_size)
{
    const float* causal  = (const float*)d_in[0];
    const float* pastkv  = (const float*)d_in[1];
    const float* wq_conv = (const float*)d_in[2];
    const float* bq_conv = (const float*)d_in[3];
    const float* wq_proj = (const float*)d_in[4];
    const float* bq_proj = (const float*)d_in[5];
    const float* wk_conv = (const float*)d_in[6];
    const float* bk_conv = (const float*)d_in[7];
    const float* wk_proj = (const float*)d_in[8];
    const float* bk_proj = (const float*)d_in[9];
    const float* wv_conv = (const float*)d_in[10];
    const float* bv_conv = (const float*)d_in[11];
    const float* wv_proj = (const float*)d_in[12];
    const float* bv_proj = (const float*)d_in[13];
    const float* w_cproj = (const float*)d_in[14];
    const float* ln_w    = (const float*)d_in[15];
    const float* w_fc    = (const float*)d_in[16];
    const float* w_mlp   = (const float*)d_in[17];
    float* out = (float*)d_out;

    float *q, *k, *v, *y0, *y1, *lp;
    cudaGetSymbolAddress((void**)&q,  g_q);
    cudaGetSymbolAddress((void**)&k,  g_k);
    cudaGetSymbolAddress((void**)&v,  g_v);
    cudaGetSymbolAddress((void**)&y0, g_y0);
    cudaGetSymbolAddress((void**)&y1, g_y1);
    cudaGetSymbolAddress((void**)&lp, g_l);

    tcl_mma_kernel<<<384, 128>>>(causal, pastkv, q, k, v,
                                 wq_conv, bq_conv, wq_proj, bq_proj,
                                 wk_conv, bk_conv, wk_proj, bk_proj,
                                 wv_conv, bv_conv, wv_proj, bv_proj);

    attn_mma_kernel<<<dim3((Fv*Tv)/256, NHv*NSPLIT, Bv), 256>>>(q, k, v, y0, y1, lp);

    epi_kernel<<<(Bv*Fv*Tv)/8, 256>>>(causal, y0, y1, lp, w_cproj, ln_w, w_fc, w_mlp, out);
}

// round 11
// speedup vs baseline: 2.2047x; 1.0914x over previous
#include <cuda_runtime.h>
#include <cuda_bf16.h>
#include <cstdint>
#include <math.h>

#define Bv 8
#define Fv 4
#define Tv 1024
#define Sv 1024
#define Cv 32
#define C2v 64
#define NHv 2
#define HDv 16
#define NSPLIT 4

// Scratch (device globals: no allocation allowed)
__device__ float g_q[Bv*Fv*Tv*Cv];    // 4 MB
__device__ float g_k[Bv*Sv*Cv];       // 1 MB
__device__ float g_v[Bv*Sv*Cv];       // 1 MB
__device__ float g_y0[Bv*Fv*Tv*Cv];   // 4 MB  (split partials, unnormalized)
__device__ float g_y1[Bv*Fv*Tv*Cv];
__device__ float g_y2[Bv*Fv*Tv*Cv];
__device__ float g_y3[Bv*Fv*Tv*Cv];
__device__ float g_l[NSPLIT*Bv*NHv*Fv*Tv];  // 1 MB (partial row sums)

__device__ __forceinline__ float gelu_f(float x) {
    return 0.5f * x * (1.0f + erff(x * 0.7071067811865476f));
}

// tanh-approx gelu (HW tanh.approx)
__device__ __forceinline__ float gelu_t(float x) {
    float u = 0.7978845608028654f * x * (1.0f + 0.044715f * x * x);
    float t;
    asm("tanh.approx.f32 %0, %1;" : "=f"(t) : "f"(u));
    return 0.5f * x * (1.0f + t);
}

__device__ __forceinline__ uint32_t f2tf32(float f) {
    uint32_t u;
    asm("cvt.rna.tf32.f32 %0, %1;" : "=r"(u) : "f"(f));
    return u;
}

__device__ __forceinline__ uint32_t pack_bf16x2(float lo, float hi) {
    __nv_bfloat162 p = __floats2bfloat162_rn(lo, hi);   // x=lo, y=hi
    return *reinterpret_cast<uint32_t*>(&p);
}

__device__ __forceinline__ void mma_tf32(float c[4], const uint32_t a[4], const uint32_t b[2]) {
    asm volatile(
        "mma.sync.aligned.m16n8k8.row.col.f32.tf32.tf32.f32 "
        "{%0,%1,%2,%3},{%4,%5,%6,%7},{%8,%9},{%0,%1,%2,%3};"
        : "+f"(c[0]), "+f"(c[1]), "+f"(c[2]), "+f"(c[3])
        : "r"(a[0]), "r"(a[1]), "r"(a[2]), "r"(a[3]), "r"(b[0]), "r"(b[1]));
}

__device__ __forceinline__ void mma_bf16(float c[4], const uint32_t a[4], const uint32_t b[2]) {
    asm volatile(
        "mma.sync.aligned.m16n8k16.row.col.f32.bf16.bf16.f32 "
        "{%0,%1,%2,%3},{%4,%5,%6,%7},{%8,%9},{%0,%1,%2,%3};"
        : "+f"(c[0]), "+f"(c[1]), "+f"(c[2]), "+f"(c[3])
        : "r"(a[0]), "r"(a[1]), "r"(a[2]), "r"(a[3]), "r"(b[0]), "r"(b[1]));
}

// ---------------------------------------------------------------------------
// TCL v2 (unchanged from round 10 — 19.5us, validated)
// ---------------------------------------------------------------------------
#define XSTR 52

__global__ __launch_bounds__(128) void tcl_mma_kernel(
    const float* __restrict__ causal, const float* __restrict__ pastkv,
    float* __restrict__ qo, float* __restrict__ ko, float* __restrict__ vo,
    const float* __restrict__ wqc, const float* __restrict__ bqc,
    const float* __restrict__ wqp, const float* __restrict__ bqp,
    const float* __restrict__ wkc, const float* __restrict__ bkc,
    const float* __restrict__ wkp, const float* __restrict__ bkp,
    const float* __restrict__ wvc, const float* __restrict__ bvc,
    const float* __restrict__ wvp, const float* __restrict__ bvp)
{
    __shared__ uint32_t Xp[128*XSTR];
    __shared__ uint32_t Wcp[64*XSTR];
    __shared__ uint32_t Wpp[32*XSTR];
    __shared__ float bcs[C2v];
    __shared__ float bps[Cv];

    const int bid = blockIdx.x;
    const int stream = bid >> 3, tile = bid & 7;
    const float *x, *wconv, *bconv, *wproj, *bproj;
    float* out;
    if (stream < 32) {
        x = causal + (long)stream*32768; out = qo + (long)stream*32768;
        wconv = wqc; bconv = bqc; wproj = wqp; bproj = bqp;
    } else if (stream < 40) {
        int n = stream - 32;
        x = pastkv + (long)n*32768; out = ko + (long)n*32768;
        wconv = wkc; bconv = bkc; wproj = wkp; bproj = bkp;
    } else {
        int n = stream - 40;
        x = pastkv + (long)n*32768; out = vo + (long)n*32768;
        wconv = wvc; bconv = bvc; wproj = wvp; bproj = bvp;
    }

    const int tid = threadIdx.x;
    const int t0 = tile * 128;

    for (int i = tid; i < 64*48; i += 128) {
        int n = i / 48, kp = i % 48;
        int tap = kp >> 4, c = (kp & 15) * 2;
        Wcp[n*XSTR + kp] = pack_bf16x2(wconv[(n*Cv + c)*3 + tap],
                                       wconv[(n*Cv + c+1)*3 + tap]);
    }
    for (int i = tid; i < 32*32; i += 128) {
        int n = i >> 5, kp = i & 31;
        Wpp[n*XSTR + kp] = pack_bf16x2(wproj[n*C2v + 2*kp], wproj[n*C2v + 2*kp+1]);
    }
    if (tid < C2v) bcs[tid] = bconv[tid];
    if (tid < Cv)  bps[tid] = bproj[tid];

    for (int i = tid; i < 128*48; i += 128) {
        int r = i / 48, kp = i % 48;
        int tap = kp >> 4, c = (kp & 15) * 2;
        int t = t0 + r - 2 + tap;
        uint32_t val = 0u;
        if (t >= 0) {
            const float* src = x + (long)t*Cv + c;
            val = pack_bf16x2(src[0], src[1]);
        }
        Xp[r*XSTR + kp] = val;
    }
    __syncthreads();

    const int w  = tid >> 5, l = tid & 31;
    const int lq = l >> 2, lr = l & 3;
    const int r0 = w * 32;

    float Cc[2][8][4];
    #pragma unroll
    for (int mt = 0; mt < 2; mt++)
        #pragma unroll
        for (int nt = 0; nt < 8; nt++)
            #pragma unroll
            for (int e = 0; e < 4; e++) Cc[mt][nt][e] = 0.f;

    #pragma unroll
    for (int ks = 0; ks < 6; ks++) {
        uint32_t a[2][4];
        #pragma unroll
        for (int mt = 0; mt < 2; mt++) {
            int rr = r0 + mt*16;
            a[mt][0] = Xp[(rr+lq)*XSTR   + ks*8 + lr];
            a[mt][1] = Xp[(rr+lq+8)*XSTR + ks*8 + lr];
            a[mt][2] = Xp[(rr+lq)*XSTR   + ks*8 + lr + 4];
            a[mt][3] = Xp[(rr+lq+8)*XSTR + ks*8 + lr + 4];
        }
        #pragma unroll
        for (int nt = 0; nt < 8; nt++) {
            uint32_t bf[2];
            bf[0] = Wcp[(nt*8+lq)*XSTR + ks*8 + lr];
            bf[1] = Wcp[(nt*8+lq)*XSTR + ks*8 + lr + 4];
            mma_bf16(Cc[0][nt], a[0], bf);
            mma_bf16(Cc[1][nt], a[1], bf);
        }
    }

    uint32_t pa[2][4][4];
    #pragma unroll
    for (int ks2 = 0; ks2 < 4; ks2++) {
        float b0 = bcs[(2*ks2)*8   + 2*lr], b1 = bcs[(2*ks2)*8   + 2*lr + 1];
        float b2 = bcs[(2*ks2+1)*8 + 2*lr], b3 = bcs[(2*ks2+1)*8 + 2*lr + 1];
        #pragma unroll
        for (int mt = 0; mt < 2; mt++) {
            pa[mt][ks2][0] = pack_bf16x2(gelu_t(Cc[mt][2*ks2][0]+b0),   gelu_t(Cc[mt][2*ks2][1]+b1));
            pa[mt][ks2][1] = pack_bf16x2(gelu_t(Cc[mt][2*ks2][2]+b0),   gelu_t(Cc[mt][2*ks2][3]+b1));
            pa[mt][ks2][2] = pack_bf16x2(gelu_t(Cc[mt][2*ks2+1][0]+b2), gelu_t(Cc[mt][2*ks2+1][1]+b3));
            pa[mt][ks2][3] = pack_bf16x2(gelu_t(Cc[mt][2*ks2+1][2]+b2), gelu_t(Cc[mt][2*ks2+1][3]+b3));
        }
    }

    float Cp[2][4][4];
    #pragma unroll
    for (int mt = 0; mt < 2; mt++)
        #pragma unroll
        for (int nt = 0; nt < 4; nt++)
            #pragma unroll
            for (int e = 0; e < 4; e++) Cp[mt][nt][e] = 0.f;

    #pragma unroll
    for (int ks2 = 0; ks2 < 4; ks2++) {
        #pragma unroll
        for (int nt = 0; nt < 4; nt++) {
            uint32_t bf[2];
            bf[0] = Wpp[(nt*8+lq)*XSTR + ks2*8 + lr];
            bf[1] = Wpp[(nt*8+lq)*XSTR + ks2*8 + lr + 4];
            mma_bf16(Cp[0][nt], pa[0][ks2], bf);
            mma_bf16(Cp[1][nt], pa[1][ks2], bf);
        }
    }

    #pragma unroll
    for (int mt = 0; mt < 2; mt++) {
        #pragma unroll
        for (int nt = 0; nt < 4; nt++) {
            int col = nt*8 + 2*lr;
            float bo0 = bps[col], bo1 = bps[col+1];
            long row = t0 + r0 + mt*16 + lq;
            *(float2*)(out + row*Cv + col)     = make_float2(Cp[mt][nt][0]+bo0, Cp[mt][nt][1]+bo1);
            *(float2*)(out + (row+8)*Cv + col) = make_float2(Cp[mt][nt][2]+bo0, Cp[mt][nt][3]+bo1);
        }
    }
}

// ---------------------------------------------------------------------------
// Attention v5: split-S x4, single-stage SMEM (whole 256-s range), exp2 domain
// (log2e folded into Q prescale -> raw EX2). 32 q rows/warp, bf16 PV.
// Grid (16, NHv*NSPLIT, Bv) = 1024 blocks.
// ---------------------------------------------------------------------------
#define CH 256         // s range per block (= Sv/NSPLIT), staged once
#define KSTR 20        // Ks row stride (floats)
#define VSTR 24        // Vp pair-row stride (u32)
#define QSCALE 0.3606737602222409f   // 0.25 * log2(e)

__global__ __launch_bounds__(256) void attn_mma_kernel(
    const float* __restrict__ q, const float* __restrict__ k,
    const float* __restrict__ v,
    float* __restrict__ y0, float* __restrict__ y1,
    float* __restrict__ y2, float* __restrict__ y3,
    float* __restrict__ lpart)
{
    __shared__ float    Ks[CH*KSTR];        // 20 KB
    __shared__ uint32_t Vp[(CH/2)*VSTR];    // 12 KB

    const int tid = threadIdx.x;
    const int w   = tid >> 5;
    const int l   = tid & 31;
    const int lq  = l >> 2;
    const int lr  = l & 3;
    const int b     = blockIdx.z;
    const int h     = blockIdx.y >> 2;
    const int split = blockIdx.y & 3;

    const int rowbase = blockIdx.x * 256 + w * 32;
    const int f  = rowbase >> 10;
    const int t0 = rowbase & 1023;
    const float* qbase = q + (((long)(b*Fv + f))*Tv + t0)*Cv + h*HDv;

    // Q fragments, prescaled by 0.25*log2(e) -> scores in log2 domain
    uint32_t qa[2][2][4];
    #pragma unroll
    for (int mt = 0; mt < 2; mt++)
        #pragma unroll
        for (int ks = 0; ks < 2; ks++) {
            int r0 = mt*16 + lq;
            int c0 = ks*8 + lr;
            qa[mt][ks][0] = f2tf32(qbase[(long)r0*Cv + c0]       * QSCALE);
            qa[mt][ks][1] = f2tf32(qbase[(long)(r0+8)*Cv + c0]   * QSCALE);
            qa[mt][ks][2] = f2tf32(qbase[(long)r0*Cv + c0+4]     * QSCALE);
            qa[mt][ks][3] = f2tf32(qbase[(long)(r0+8)*Cv + c0+4] * QSCALE);
        }

    float O[2][2][4];
    #pragma unroll
    for (int i = 0; i < 2; i++)
        #pragma unroll
        for (int j = 0; j < 2; j++)
            #pragma unroll
            for (int e = 0; e < 4; e++) O[i][j][e] = 0.f;
    float ls[4] = {0.f, 0.f, 0.f, 0.f};

    const int s0 = split * CH;
    const float* kb = k + ((long)b*Sv + s0)*Cv + h*HDv;
    const float* vb = v + ((long)b*Sv + s0)*Cv + h*HDv;

    // Stage once (no loop; SMEM read-only afterwards)
    for (int i = tid; i < CH*16; i += 256) {
        int s = i >> 4, d = i & 15;
        Ks[s*KSTR + d] = __uint_as_float(f2tf32(kb[(long)s*Cv + d]));
    }
    for (int i = tid; i < (CH/2)*16; i += 256) {
        int s2 = i >> 4, d = i & 15;
        Vp[s2*VSTR + d] = pack_bf16x2(vb[(long)(2*s2)*Cv + d],
                                      vb[(long)(2*s2+1)*Cv + d]);
    }
    __syncthreads();

    #pragma unroll 4
    for (int ntp = 0; ntp < CH/16; ntp++) {     // 16-s slices
        uint32_t pa[2][4];
        #pragma unroll
        for (int half = 0; half < 2; half++) {
            int snt = ntp*16 + half*8;
            uint32_t kf[2][2];
            #pragma unroll
            for (int ks = 0; ks < 2; ks++) {
                int dbase = ks*8 + lr;
                kf[ks][0] = __float_as_uint(Ks[(snt + lq)*KSTR + dbase]);
                kf[ks][1] = __float_as_uint(Ks[(snt + lq)*KSTR + dbase + 4]);
            }
            #pragma unroll
            for (int mt = 0; mt < 2; mt++) {
                float c[4] = {0.f, 0.f, 0.f, 0.f};
                mma_tf32(c, qa[mt][0], kf[0]);
                mma_tf32(c, qa[mt][1], kf[1]);
                float e0 = exp2f(fminf(c[0], 115.f));
                float e1 = exp2f(fminf(c[1], 115.f));
                float e2 = exp2f(fminf(c[2], 115.f));
                float e3 = exp2f(fminf(c[3], 115.f));
                ls[mt*2]   += e0 + e1;
                ls[mt*2+1] += e2 + e3;
                pa[mt][half*2 + 0] = pack_bf16x2(e0, e1);
                pa[mt][half*2 + 1] = pack_bf16x2(e2, e3);
            }
        }
        int s2base = ntp * 8;
        #pragma unroll
        for (int dn = 0; dn < 2; dn++) {
            uint32_t vf[2];
            vf[0] = Vp[(s2base + lr)*VSTR + dn*8 + lq];
            vf[1] = Vp[(s2base + lr + 4)*VSTR + dn*8 + lq];
            mma_bf16(O[0][dn], pa[0], vf);
            mma_bf16(O[1][dn], pa[1], vf);
        }
    }

    #pragma unroll
    for (int i = 0; i < 4; i++) {
        ls[i] += __shfl_xor_sync(0xffffffffu, ls[i], 1);
        ls[i] += __shfl_xor_sync(0xffffffffu, ls[i], 2);
    }

    float* ybuf = (split == 0) ? y0 : (split == 1) ? y1 : (split == 2) ? y2 : y3;
    float* yout = ybuf + (((long)(b*Fv + f))*Tv + t0)*Cv + h*HDv;
    #pragma unroll
    for (int mt = 0; mt < 2; mt++)
        #pragma unroll
        for (int dn = 0; dn < 2; dn++) {
            int d0 = dn*8 + 2*lr;
            int r0 = mt*16 + lq;
            *(float2*)(yout + (long)r0*Cv + d0)     = make_float2(O[mt][dn][0], O[mt][dn][1]);
            *(float2*)(yout + (long)(r0+8)*Cv + d0) = make_float2(O[mt][dn][2], O[mt][dn][3]);
        }

    if (lr == 0) {
        long lb = ((long)(split*Bv + b)*NHv + h)*(Fv*Tv) + rowbase;
        #pragma unroll
        for (int mt = 0; mt < 2; mt++) {
            lpart[lb + mt*16 + lq]     = ls[mt*2];
            lpart[lb + mt*16 + lq + 8] = ls[mt*2+1];
        }
    }
}

// ---------------------------------------------------------------------------
// Epilogue: combines 4 split partials, then cproj+LN+MLP (body unchanged).
// ---------------------------------------------------------------------------
__global__ void epi_kernel(const float* __restrict__ causal,
                           const float* __restrict__ y0, const float* __restrict__ y1,
                           const float* __restrict__ y2, const float* __restrict__ y3,
                           const float* __restrict__ lpart,
                           const float* __restrict__ wc, const float* __restrict__ lnw,
                           const float* __restrict__ wfc, const float* __restrict__ wmp,
                           float* __restrict__ out)
{
    __shared__ float wcs[32*32];
    __shared__ float wfcs[32*32];
    __shared__ float wmps[32*32];
    __shared__ float lns[32];
    __shared__ float stage[8][32];

    int tid = threadIdx.x;
    for (int i = tid; i < 1024; i += 256) {
        int a = i >> 5, bcol = i & 31;
        wcs[i]  = wc[bcol*32 + a];
        wfcs[i] = wfc[bcol*32 + a];
        wmps[i] = wmp[bcol*32 + a];
    }
    if (tid < 32) lns[tid] = lnw[tid];
    __syncthreads();

    int wid = tid >> 5, lane = tid & 31;
    long row = (long)blockIdx.x * 8 + wid;
    int b  = (int)(row >> 12);
    int ft = (int)(row & 4095);
    int h  = lane >> 4;

    const long LSTRIDE = (long)Bv*NHv*Fv*Tv;
    long lidx = ((long)b*NHv + h)*(Fv*Tv) + ft;
    float lsum = lpart[lidx] + lpart[LSTRIDE + lidx]
               + lpart[2*LSTRIDE + lidx] + lpart[3*LSTRIDE + lidx];
    float yc = (y0[row*32 + lane] + y1[row*32 + lane]
              + y2[row*32 + lane] + y3[row*32 + lane]) / lsum;
    stage[wid][lane] = yc;
    __syncwarp();

    float o = causal[row*32 + lane];
    #pragma unroll
    for (int j = 0; j < 32; j++) o += stage[wid][j] * wcs[j*32 + lane];
    __syncwarp();

    float sum = o, sq = o*o;
    #pragma unroll
    for (int off = 16; off; off >>= 1) {
        sum += __shfl_xor_sync(0xffffffffu, sum, off);
        sq  += __shfl_xor_sync(0xffffffffu, sq, off);
    }
    float mu  = sum * (1.0f/32.0f);
    float var = sq  * (1.0f/32.0f) - mu*mu;
    float hn = (o - mu) * rsqrtf(var + 1e-5f) * lns[lane];

    stage[wid][lane] = hn;
    __syncwarp();
    float g = 0.f;
    #pragma unroll
    for (int j = 0; j < 32; j++) g += stage[wid][j] * wfcs[j*32 + lane];
    __syncwarp();
    g = gelu_f(g);
    stage[wid][lane] = g;
    __syncwarp();
    float mlp = 0.f;
    #pragma unroll
    for (int j = 0; j < 32; j++) mlp += stage[wid][j] * wmps[j*32 + lane];

    out[row*32 + lane] = o + mlp;
}

// ---------------------------------------------------------------------------
extern "C" void kernel_launch(void* const* d_in, const int* in_sizes, int n_in,
                              void* d_out, int out_size)
{
    const float* causal  = (const float*)d_in[0];
    const float* pastkv  = (const float*)d_in[1];
    const float* wq_conv = (const float*)d_in[2];
    const float* bq_conv = (const float*)d_in[3];
    const float* wq_proj = (const float*)d_in[4];
    const float* bq_proj = (const float*)d_in[5];
    const float* wk_conv = (const float*)d_in[6];
    const float* bk_conv = (const float*)d_in[7];
    const float* wk_proj = (const float*)d_in[8];
    const float* bk_proj = (const float*)d_in[9];
    const float* wv_conv = (const float*)d_in[10];
    const float* bv_conv = (const float*)d_in[11];
    const float* wv_proj = (const float*)d_in[12];
    const float* bv_proj = (const float*)d_in[13];
    const float* w_cproj = (const float*)d_in[14];
    const float* ln_w    = (const float*)d_in[15];
    const float* w_fc    = (const float*)d_in[16];
    const float* w_mlp   = (const float*)d_in[17];
    float* out = (float*)d_out;

    float *q, *k, *v, *y0, *y1, *y2, *y3, *lp;
    cudaGetSymbolAddress((void**)&q,  g_q);
    cudaGetSymbolAddress((void**)&k,  g_k);
    cudaGetSymbolAddress((void**)&v,  g_v);
    cudaGetSymbolAddress((void**)&y0, g_y0);
    cudaGetSymbolAddress((void**)&y1, g_y1);
    cudaGetSymbolAddress((void**)&y2, g_y2);
    cudaGetSymbolAddress((void**)&y3, g_y3);
    cudaGetSymbolAddress((void**)&lp, g_l);

    tcl_mma_kernel<<<384, 128>>>(causal, pastkv, q, k, v,
                                 wq_conv, bq_conv, wq_proj, bq_proj,
                                 wk_conv, bk_conv, wk_proj, bk_proj,
                                 wv_conv, bv_conv, wv_proj, bv_proj);

    // 256-row q tiles, S split in 4: grid (16, NHv*NSPLIT, Bv) = 1024 blocks
    attn_mma_kernel<<<dim3((Fv*Tv)/256, NHv*NSPLIT, Bv), 256>>>(q, k, v, y0, y1, y2, y3, lp);

    epi_kernel<<<(Bv*Fv*Tv)/8, 256>>>(causal, y0, y1, y2, y3, lp,
                                      w_cproj, ln_w, w_fc, w_mlp, out);
}